// round 1
// baseline (speedup 1.0000x reference)
#include <cuda_runtime.h>

#define NUM_ENT   14541
#define EMBED_D   200
#define D2        100          // D/2 (packed f32x2 along D)
#define BATCH     256
#define TILE_B    64
#define TILE_N    131          // 111 * 131 == 14541 exactly
#define N_TILES   111
#define B_TILES   4
#define THREADS   256
#define OBJ_PITCH 65           // padded (2-way store conflict max)
#define ENT_PITCH 131          // odd pitch -> 2-way store conflict max
#define SMEM_ULL  (D2 * ENT_PITCH + D2 * OBJ_PITCH)   // 19600
#define SMEM_BYTES (SMEM_ULL * 8)                      // 156800

// Precomputed obj_emb = ent[sub[b]] + rel[rel[b]]  -> [BATCH][EMBED_D]
__device__ float g_obj[BATCH * EMBED_D];

__global__ void obj_kernel(const float* __restrict__ ent,
                           const float* __restrict__ rel_e,
                           const int* __restrict__ sub,
                           const int* __restrict__ rel) {
    int idx = blockIdx.x * blockDim.x + threadIdx.x;
    if (idx < BATCH * EMBED_D) {
        int b = idx / EMBED_D;
        int d = idx - b * EMBED_D;
        g_obj[idx] = ent[sub[b] * EMBED_D + d] + rel_e[rel[b] * EMBED_D + d];
    }
}

__device__ __forceinline__ unsigned long long addf2(unsigned long long a,
                                                    unsigned long long b) {
    unsigned long long r;
    asm("add.rn.f32x2 %0, %1, %2;" : "=l"(r) : "l"(a), "l"(b));
    return r;
}

__global__ void __launch_bounds__(THREADS, 1)
transe_kernel(const float* __restrict__ ent, float* __restrict__ out) {
    extern __shared__ unsigned long long smem[];
    unsigned long long* ent_s = smem;                     // [D2][ENT_PITCH], pre-negated
    unsigned long long* obj_s = smem + D2 * ENT_PITCH;    // [D2][OBJ_PITCH]

    const int tid = threadIdx.x;
    const int n0  = blockIdx.x * TILE_N;
    const int b0  = blockIdx.y * TILE_B;

    // ---- load ent tile, pre-negated, transposed to [d2][n] packed f32x2 ----
    // mapping: consecutive tid -> consecutive d2 (coalesced gmem reads)
    for (int idx = tid; idx < TILE_N * D2; idx += THREADS) {
        int n  = idx / D2;
        int d2 = idx - n * D2;
        unsigned long long v =
            *reinterpret_cast<const unsigned long long*>(ent + (n0 + n) * EMBED_D + 2 * d2);
        ent_s[d2 * ENT_PITCH + n] = v ^ 0x8000000080000000ULL;  // negate both halves
    }
    // ---- load obj tile [d2][b] ----
    for (int idx = tid; idx < TILE_B * D2; idx += THREADS) {
        int b  = idx / D2;
        int d2 = idx - b * D2;
        obj_s[d2 * OBJ_PITCH + b] =
            *reinterpret_cast<const unsigned long long*>(g_obj + (b0 + b) * EMBED_D + 2 * d2);
    }
    __syncthreads();

    const int tn = tid & 31;   // n-lane   (covers 4*32 = 128 of 131 cols)
    const int wg = tid >> 5;   // b-group  (8 warps, each covers b = wg + 8*i)
    const unsigned long long MASK = 0x7FFFFFFF7FFFFFFFULL;

    unsigned long long acc[8][4];
#pragma unroll
    for (int i = 0; i < 8; i++)
#pragma unroll
        for (int j = 0; j < 4; j++) acc[i][j] = 0ULL;

#pragma unroll 2
    for (int d2 = 0; d2 < D2; d2++) {
        unsigned long long o[8], e[4];
#pragma unroll
        for (int i = 0; i < 8; i++) o[i] = obj_s[d2 * OBJ_PITCH + wg + 8 * i];   // broadcast
#pragma unroll
        for (int j = 0; j < 4; j++) e[j] = ent_s[d2 * ENT_PITCH + tn + 32 * j];  // stride-1
#pragma unroll
        for (int i = 0; i < 8; i++) {
#pragma unroll
            for (int j = 0; j < 4; j++) {
                unsigned long long t = addf2(o[i], e[j]) & MASK;  // |obj - ent| packed
                acc[i][j] = addf2(acc[i][j], t);
            }
        }
    }

    // ---- epilogue: main 128 columns ----
#pragma unroll
    for (int i = 0; i < 8; i++) {
        int b = b0 + wg + 8 * i;
#pragma unroll
        for (int j = 0; j < 4; j++) {
            float2 f = *reinterpret_cast<float2*>(&acc[i][j]);
            float dist = f.x + f.y;
            out[b * NUM_ENT + (n0 + tn + 32 * j)] =
                __fdividef(1.0f, 1.0f + __expf(dist - 9.0f));
        }
    }

    // ---- strip: remaining 3 columns (n = 128..130), threads 0..191 ----
    if (tid < TILE_B * 3) {
        int sb = tid / 3;
        int sn = 128 + (tid - sb * 3);
        unsigned long long sacc = 0ULL;
#pragma unroll 4
        for (int d2 = 0; d2 < D2; d2++) {
            unsigned long long t =
                addf2(obj_s[d2 * OBJ_PITCH + sb], ent_s[d2 * ENT_PITCH + sn]) & MASK;
            sacc = addf2(sacc, t);
        }
        float2 f = *reinterpret_cast<float2*>(&sacc);
        float dist = f.x + f.y;
        out[(b0 + sb) * NUM_ENT + (n0 + sn)] =
            __fdividef(1.0f, 1.0f + __expf(dist - 9.0f));
    }
}

extern "C" void kernel_launch(void* const* d_in, const int* in_sizes, int n_in,
                              void* d_out, int out_size) {
    const float* ent   = (const float*)d_in[0];
    const float* rel_e = (const float*)d_in[1];
    const int*   sub   = (const int*)d_in[2];
    const int*   rel   = (const int*)d_in[3];
    float* out = (float*)d_out;

    cudaFuncSetAttribute(transe_kernel,
                         cudaFuncAttributeMaxDynamicSharedMemorySize, SMEM_BYTES);

    obj_kernel<<<(BATCH * EMBED_D + 255) / 256, 256>>>(ent, rel_e, sub, rel);
    transe_kernel<<<dim3(N_TILES, B_TILES), THREADS, SMEM_BYTES>>>(ent, out);
}

// round 2
// speedup vs baseline: 1.0025x; 1.0025x over previous
#include <cuda_runtime.h>

#define NUM_ENT   14541
#define EMBED_D   200
#define D2        100          // D/2 (packed f32x2 along D)
#define D2_HALF   50
#define BATCH     256
#define TILE_B    64
#define TILE_N    131          // 111 * 131 == 14541 exactly
#define N_TILES   111
#define B_TILES   4
#define THREADS   512
#define OBJ_PITCH 65
#define ENT_PITCH 131
#define SMEM_ULL  (D2 * ENT_PITCH + D2 * OBJ_PITCH)   // 19600
#define SMEM_BYTES (SMEM_ULL * 8)                      // 156800

// Precomputed obj_emb = ent[sub[b]] + rel[rel[b]]  -> [BATCH][EMBED_D]
__device__ float g_obj[BATCH * EMBED_D];

__global__ void obj_kernel(const float* __restrict__ ent,
                           const float* __restrict__ rel_e,
                           const int* __restrict__ sub,
                           const int* __restrict__ rel) {
    int idx = blockIdx.x * blockDim.x + threadIdx.x;
    if (idx < BATCH * EMBED_D) {
        int b = idx / EMBED_D;
        int d = idx - b * EMBED_D;
        g_obj[idx] = ent[sub[b] * EMBED_D + d] + rel_e[rel[b] * EMBED_D + d];
    }
}

__device__ __forceinline__ unsigned long long addf2(unsigned long long a,
                                                    unsigned long long b) {
    unsigned long long r;
    asm("add.rn.f32x2 %0, %1, %2;" : "=l"(r) : "l"(a), "l"(b));
    return r;
}

__global__ void __launch_bounds__(THREADS, 1)
transe_kernel(const float* __restrict__ ent, float* __restrict__ out) {
    extern __shared__ unsigned long long smem[];
    unsigned long long* ent_s = smem;                     // [D2][ENT_PITCH], pre-negated
    unsigned long long* obj_s = smem + D2 * ENT_PITCH;    // [D2][OBJ_PITCH]

    const int tid = threadIdx.x;
    const int n0  = blockIdx.x * TILE_N;
    const int b0  = blockIdx.y * TILE_B;

    // ---- load ent tile, pre-negated, transposed to [d2][n] packed f32x2 ----
    for (int idx = tid; idx < TILE_N * D2; idx += THREADS) {
        int n  = idx / D2;
        int d2 = idx - n * D2;
        unsigned long long v =
            *reinterpret_cast<const unsigned long long*>(ent + (n0 + n) * EMBED_D + 2 * d2);
        ent_s[d2 * ENT_PITCH + n] = v ^ 0x8000000080000000ULL;  // negate both halves
    }
    // ---- load obj tile [d2][b] ----
    for (int idx = tid; idx < TILE_B * D2; idx += THREADS) {
        int b  = idx / D2;
        int d2 = idx - b * D2;
        obj_s[d2 * OBJ_PITCH + b] =
            *reinterpret_cast<const unsigned long long*>(g_obj + (b0 + b) * EMBED_D + 2 * d2);
    }
    __syncthreads();

    const int tn   = tid & 31;         // n-lane (covers 4*32 = 128 of 131 cols)
    const int wg   = (tid >> 5) & 7;   // b-group
    const int half = tid >> 8;         // 0: d2 [0,50), 1: d2 [50,100)
    const int d2lo = half * D2_HALF;
    const unsigned long long MASK = 0x7FFFFFFF7FFFFFFFULL;

    unsigned long long acc[8][4];
#pragma unroll
    for (int i = 0; i < 8; i++)
#pragma unroll
        for (int j = 0; j < 4; j++) acc[i][j] = 0ULL;

#pragma unroll 2
    for (int d2 = d2lo; d2 < d2lo + D2_HALF; d2++) {
        unsigned long long o[8], e[4];
#pragma unroll
        for (int i = 0; i < 8; i++) o[i] = obj_s[d2 * OBJ_PITCH + wg + 8 * i];   // broadcast
#pragma unroll
        for (int j = 0; j < 4; j++) e[j] = ent_s[d2 * ENT_PITCH + tn + 32 * j];  // stride-1
#pragma unroll
        for (int i = 0; i < 8; i++) {
#pragma unroll
            for (int j = 0; j < 4; j++) {
                unsigned long long t = addf2(o[i], e[j]) & MASK;  // |obj - ent| packed
                acc[i][j] = addf2(acc[i][j], t);
            }
        }
    }

    // ---- strip: remaining 3 columns (n = 128..130), full D, threads 0..191 ----
    if (tid < TILE_B * 3) {
        int sb = tid / 3;
        int sn = 128 + (tid - sb * 3);
        unsigned long long sacc = 0ULL;
#pragma unroll 4
        for (int d2 = 0; d2 < D2; d2++) {
            unsigned long long t =
                addf2(obj_s[d2 * OBJ_PITCH + sb], ent_s[d2 * ENT_PITCH + sn]) & MASK;
            sacc = addf2(sacc, t);
        }
        float2 f = *reinterpret_cast<float2*>(&sacc);
        float dist = f.x + f.y;
        out[(b0 + sb) * NUM_ENT + (n0 + sn)] =
            __fdividef(1.0f, 1.0f + __expf(dist - 9.0f));
    }

    // ---- combine halves: upper writes partials, lower reduces + outputs ----
    __syncthreads();                       // smem tile reads done; safe to reuse
    unsigned long long* part = smem;       // [32][256] conflict-free layout (64 KB)
    const int t8 = tid & 255;

    if (half == 1) {
#pragma unroll
        for (int i = 0; i < 8; i++)
#pragma unroll
            for (int j = 0; j < 4; j++)
                part[(i * 4 + j) * 256 + t8] = acc[i][j];
    }
    __syncthreads();

    if (half == 0) {
#pragma unroll
        for (int i = 0; i < 8; i++) {
            int b = b0 + wg + 8 * i;
#pragma unroll
            for (int j = 0; j < 4; j++) {
                unsigned long long s = addf2(acc[i][j], part[(i * 4 + j) * 256 + t8]);
                float2 f = *reinterpret_cast<float2*>(&s);
                float dist = f.x + f.y;
                out[b * NUM_ENT + (n0 + tn + 32 * j)] =
                    __fdividef(1.0f, 1.0f + __expf(dist - 9.0f));
            }
        }
    }
}

extern "C" void kernel_launch(void* const* d_in, const int* in_sizes, int n_in,
                              void* d_out, int out_size) {
    const float* ent   = (const float*)d_in[0];
    const float* rel_e = (const float*)d_in[1];
    const int*   sub   = (const int*)d_in[2];
    const int*   rel   = (const int*)d_in[3];
    float* out = (float*)d_out;

    cudaFuncSetAttribute(transe_kernel,
                         cudaFuncAttributeMaxDynamicSharedMemorySize, SMEM_BYTES);

    obj_kernel<<<(BATCH * EMBED_D + 255) / 256, 256>>>(ent, rel_e, sub, rel);
    transe_kernel<<<dim3(N_TILES, B_TILES), THREADS, SMEM_BYTES>>>(ent, out);
}

// round 3
// speedup vs baseline: 1.0075x; 1.0050x over previous
#include <cuda_runtime.h>

#define NUM_ENT   14541
#define EMBED_D   200
#define D2        100          // D/2 (packed f32x2 along D)
#define D2_HALF   50
#define BATCH     256
#define TILE_B    64
#define TILE_N    131          // 111 * 131 == 14541 exactly
#define N_TILES   111
#define B_TILES   4
#define THREADS   512
#define OBJ_PITCH 65
#define ENT_PITCH 131
#define SMEM_ULL  (D2 * ENT_PITCH + D2 * OBJ_PITCH)   // 19600
#define SMEM_BYTES (SMEM_ULL * 8)                      // 156800

typedef unsigned long long ull;

// Precomputed obj_emb = ent[sub[b]] + rel[rel[b]]  -> [BATCH][EMBED_D]
__device__ float g_obj[BATCH * EMBED_D];

__global__ void obj_kernel(const float* __restrict__ ent,
                           const float* __restrict__ rel_e,
                           const int* __restrict__ sub,
                           const int* __restrict__ rel) {
    int idx = blockIdx.x * blockDim.x + threadIdx.x;
    if (idx < BATCH * EMBED_D) {
        int b = idx / EMBED_D;
        int d = idx - b * EMBED_D;
        g_obj[idx] = ent[sub[b] * EMBED_D + d] + rel_e[rel[b] * EMBED_D + d];
    }
}

__device__ __forceinline__ ull addf2(ull a, ull b) {
    ull r;
    asm("add.rn.f32x2 %0, %1, %2;" : "=l"(r) : "l"(a), "l"(b));
    return r;
}

__global__ void __launch_bounds__(THREADS, 1)
transe_kernel(const float* __restrict__ ent, float* __restrict__ out) {
    extern __shared__ ull smem[];
    ull* ent_s = smem;                     // [D2][ENT_PITCH], pre-negated
    ull* obj_s = smem + D2 * ENT_PITCH;    // [D2][OBJ_PITCH]

    const int tid = threadIdx.x;
    const int n0  = blockIdx.x * TILE_N;
    const int b0  = blockIdx.y * TILE_B;

    // ---- load ent tile, pre-negated, transposed to [d2][n] packed f32x2 ----
    for (int idx = tid; idx < TILE_N * D2; idx += THREADS) {
        int n  = idx / D2;
        int d2 = idx - n * D2;
        ull v = *reinterpret_cast<const ull*>(ent + (n0 + n) * EMBED_D + 2 * d2);
        ent_s[d2 * ENT_PITCH + n] = v ^ 0x8000000080000000ULL;  // negate both halves
    }
    // ---- load obj tile [d2][b] ----
    for (int idx = tid; idx < TILE_B * D2; idx += THREADS) {
        int b  = idx / D2;
        int d2 = idx - b * D2;
        obj_s[d2 * OBJ_PITCH + b] =
            *reinterpret_cast<const ull*>(g_obj + (b0 + b) * EMBED_D + 2 * d2);
    }
    __syncthreads();

    const int tn   = tid & 31;         // n-lane (covers 4*32 = 128 of 131 cols)
    const int wg   = (tid >> 5) & 7;   // b-group
    const int half = tid >> 8;         // 0: d2 [0,50), 1: d2 [50,100)
    const int d2lo = half * D2_HALF;
    const ull MASK = 0x7FFFFFFF7FFFFFFFULL;

    ull acc[32];
#pragma unroll
    for (int k = 0; k < 32; k++) acc[k] = 0ULL;

    // ---- mainloop: hand-interleaved fma/alu schedule via volatile asm ----
    // pair k = (i = k>>2 for b, j = k&3 for n)
    // stage F: t_k = o[i] + e_neg[j]        (fma pipe)
    // stage A: u_{k-1} = t_{k-1} & MASK     (alu pipe, 2x LOP3)
    // stage F: acc_{k-2} += u_{k-2}         (fma pipe)
    // volatile pins the F,A,F interleave so convoyed warps alternate pipes.
#pragma unroll 1
    for (int d2 = d2lo; d2 < d2lo + D2_HALF; d2++) {
        ull o[8], e[4];
#pragma unroll
        for (int i = 0; i < 8; i++) o[i] = obj_s[d2 * OBJ_PITCH + wg + 8 * i];   // broadcast
#pragma unroll
        for (int j = 0; j < 4; j++) e[j] = ent_s[d2 * ENT_PITCH + tn + 32 * j];  // stride-1

        ull t[2], u[2];
#pragma unroll
        for (int k = 0; k < 34; k++) {
            if (k < 32)
                asm volatile("add.rn.f32x2 %0, %1, %2;"
                             : "=l"(t[k & 1]) : "l"(o[k >> 2]), "l"(e[k & 3]));
            if (k >= 1 && k < 33)
                asm volatile("and.b64 %0, %1, %2;"
                             : "=l"(u[(k - 1) & 1]) : "l"(t[(k - 1) & 1]), "l"(MASK));
            if (k >= 2)
                asm volatile("add.rn.f32x2 %0, %0, %1;"
                             : "+l"(acc[k - 2]) : "l"(u[(k - 2) & 1]));
        }
    }

    // ---- strip: remaining 3 columns (n = 128..130), full D, threads 0..191 ----
    if (tid < TILE_B * 3) {
        int sb = tid / 3;
        int sn = 128 + (tid - sb * 3);
        ull sacc = 0ULL;
#pragma unroll 4
        for (int d2 = 0; d2 < D2; d2++) {
            ull tt = addf2(obj_s[d2 * OBJ_PITCH + sb], ent_s[d2 * ENT_PITCH + sn]) & MASK;
            sacc = addf2(sacc, tt);
        }
        float2 f = *reinterpret_cast<float2*>(&sacc);
        float dist = f.x + f.y;
        out[(b0 + sb) * NUM_ENT + (n0 + sn)] =
            __fdividef(1.0f, 1.0f + __expf(dist - 9.0f));
    }

    // ---- combine halves: upper writes partials, lower reduces + outputs ----
    __syncthreads();                       // smem tile reads done; safe to reuse
    ull* part = smem;                      // [32][256] conflict-free layout (64 KB)
    const int t8 = tid & 255;

    if (half == 1) {
#pragma unroll
        for (int k = 0; k < 32; k++)
            part[k * 256 + t8] = acc[k];
    }
    __syncthreads();

    if (half == 0) {
#pragma unroll
        for (int k = 0; k < 32; k++) {
            int i = k >> 2, j = k & 3;
            int b = b0 + wg + 8 * i;
            ull s = addf2(acc[k], part[k * 256 + t8]);
            float2 f = *reinterpret_cast<float2*>(&s);
            float dist = f.x + f.y;
            out[b * NUM_ENT + (n0 + tn + 32 * j)] =
                __fdividef(1.0f, 1.0f + __expf(dist - 9.0f));
        }
    }
}

extern "C" void kernel_launch(void* const* d_in, const int* in_sizes, int n_in,
                              void* d_out, int out_size) {
    const float* ent   = (const float*)d_in[0];
    const float* rel_e = (const float*)d_in[1];
    const int*   sub   = (const int*)d_in[2];
    const int*   rel   = (const int*)d_in[3];
    float* out = (float*)d_out;

    cudaFuncSetAttribute(transe_kernel,
                         cudaFuncAttributeMaxDynamicSharedMemorySize, SMEM_BYTES);

    obj_kernel<<<(BATCH * EMBED_D + 255) / 256, 256>>>(ent, rel_e, sub, rel);
    transe_kernel<<<dim3(N_TILES, B_TILES), THREADS, SMEM_BYTES>>>(ent, out);
}